// round 8
// baseline (speedup 1.0000x reference)
#include <cuda_runtime.h>
#include <cuda_bf16.h>
#include <cstdint>

// ---------------- problem constants ----------------
#define D_    64
#define HW_   4096
#define K_    512
#define NPTS  131072
#define NELEM 8388608LL

// Provable candidate window: ulp(x+y) <= 2*ulp(128)=3.05e-5 for x<256,
// + 2*eps_screen (3-pass bf16 split) -> 4.1e-5 with margin. (Validated R6/R7.)
#define W0 4.1e-5f

#define MTPB   512
#define MGRID  148
#define NTILES (NPTS / 128)   // 1024

// ---- smem byte offsets (A/B tiles 1024-aligned for SW128) ----
#define SM_Y     0        // 512 f32
#define SM_BKF   2048     // 128 int
#define SM_FLAG  2560     // 128 int
#define SM_RED   3072     // 16 f32
#define SM_M1    3136     // 128*2 f32
#define SM_M2    4160     // 128*2 f32
#define SM_K1    5184     // 128*2 int
#define SM_Z     6208     // 128*65 f32 (padded rows)
#define SM_AHI   39936    // 128 rows * 128 B  bf16 z-hi  (SW128)
#define SM_ALO   56320    // 128 rows * 128 B  bf16 z-lo  (SW128)
#define SM_BH    72704    // 512 rows * 128 B  bf16 cb-hi (SW128)
#define SM_BL    138240   // 512 rows * 128 B  bf16 cb-lo (SW128)
#define SMEM_TOTAL 203776 // ~199 KB -> 1 CTA/SM

// ---------------- device globals (zero-init; finalize resets) ----------------
__device__ double g_loss_accum;
__device__ int    g_flag_count;
__device__ int    g_worklist[NPTS];
__device__ float  g_y[K_];

#define SWZ128(off) ((off) ^ (((off) >> 3) & 0x70))

__device__ __forceinline__ uint32_t smem_u32_of(const void* p) {
    uint32_t a;
    asm("{ .reg .u64 t; cvta.to.shared.u64 t, %1; cvt.u32.u64 %0, t; }"
        : "=r"(a) : "l"(p));
    return a;
}
__device__ __forceinline__ void mma_bf16(float* c, const uint32_t* a,
                                         uint32_t b0, uint32_t b1) {
    asm volatile(
        "mma.sync.aligned.m16n8k16.row.col.f32.bf16.bf16.f32 "
        "{%0,%1,%2,%3}, {%4,%5,%6,%7}, {%8,%9}, {%0,%1,%2,%3};"
        : "+f"(c[0]), "+f"(c[1]), "+f"(c[2]), "+f"(c[3])
        : "r"(a[0]), "r"(a[1]), "r"(a[2]), "r"(a[3]), "r"(b0), "r"(b1));
}
__device__ __forceinline__ void ldsm_x4(uint32_t* r, uint32_t addr) {
    asm volatile(
        "ldmatrix.sync.aligned.m8n8.x4.shared.b16 {%0,%1,%2,%3}, [%4];"
        : "=r"(r[0]), "=r"(r[1]), "=r"(r[2]), "=r"(r[3]) : "r"(addr));
}
__device__ __forceinline__ uint32_t pack_bf16x2(float lo, float hi) {
    uint32_t u;
    asm("cvt.rn.bf16x2.f32 %0, %1, %2;" : "=r"(u) : "f"(hi), "f"(lo));
    return u;
}
// Merge candidate sets {(m1,k1), m2} U {(om1,ok1), om2}; ties -> smaller index.
__device__ __forceinline__ void merge3(float& m1, int& k1, float& m2,
                                       float om1, int ok1, float om2) {
    if (om1 < m1 || (om1 == m1 && ok1 < k1)) {
        m2 = fminf(m1, om2);
        m1 = om1; k1 = ok1;
    } else {
        m2 = fminf(m2, om1);
    }
}

// ---------------- main: persistent, bf16 3-pass split screen ----------------
__global__ __launch_bounds__(MTPB, 1)
void vq_main_kernel(const float* __restrict__ z,
                    const float* __restrict__ cb,
                    float* __restrict__ out) {
    extern __shared__ char smem[];
    const uint32_t smb = smem_u32_of(smem);
    float* s_y    = (float*)(smem + SM_Y);
    int*   s_bkf  = (int*)(smem + SM_BKF);
    int*   s_flag = (int*)(smem + SM_FLAG);
    float* s_red  = (float*)(smem + SM_RED);
    float* s_m1   = (float*)(smem + SM_M1);
    float* s_m2   = (float*)(smem + SM_M2);
    int*   s_k1   = (int*)(smem + SM_K1);
    float* s_z    = (float*)(smem + SM_Z);     // [128][65]

    const int tid  = threadIdx.x;
    const int wid  = tid >> 5;
    const int lane = tid & 31;
    const int g    = lane >> 2;
    const int tg   = lane & 3;
    const int p    = tid & 127;   // staging/output point
    const int q4   = tid >> 7;    // staging/output channel quarter (0..3)

    // ---- stage B once: one code per thread ----
    {
        const int k = tid;        // 0..511
        const float4* e4 = (const float4*)(cb + k * D_);
        float ev[D_];
        #pragma unroll
        for (int i = 0; i < 16; i++) {
            float4 v = __ldg(e4 + i);
            ev[4*i] = v.x; ev[4*i+1] = v.y; ev[4*i+2] = v.z; ev[4*i+3] = v.w;
        }
        float s = 0.f;
        #pragma unroll
        for (int i = 0; i < D_; i++) s = __fadd_rn(s, __fmul_rn(ev[i], ev[i]));
        s_y[k] = s;
        if (blockIdx.x == 0) g_y[k] = s;
        #pragma unroll
        for (int j = 0; j < 32; j++) {
            float v0 = ev[2*j], v1 = ev[2*j+1];
            float h0 = __bfloat162float(__float2bfloat16(v0));
            float h1 = __bfloat162float(__float2bfloat16(v1));
            uint32_t off = (uint32_t)(k * 128 + j * 4);
            *(uint32_t*)(smem + SM_BH + SWZ128(off)) = pack_bf16x2(h0, h1);
            *(uint32_t*)(smem + SM_BL + SWZ128(off)) = pack_bf16x2(v0 - h0, v1 - h1);
        }
    }
    __syncthreads();

    // warp roles: point rows (wid>>1)*16 + g / +8 ; code half nh
    const int row0 = (wid >> 1) * 16 + g;
    const int nh   = wid & 1;

    // ldmatrix lane addresses (per-thread constant column part)
    const int lr = lane & 7;         // row within 8-row block
    const int ms = lane >> 3;        // matrix select 0..3
    const uint32_t colx0 = (uint32_t)((ms * 16) ^ (lr << 4));        // k-bytes 0..63
    const uint32_t colx1 = (uint32_t)((64 + ms * 16) ^ (lr << 4));   // k-bytes 64..127
    const uint32_t browz = (uint32_t)((nh * 256 + lr) * 128);

    for (int tile = blockIdx.x; tile < NTILES; tile += gridDim.x) {
        const int base = tile * 128;
        const int b    = base >> 12;
        const int hw0  = base & (HW_ - 1);
        const float* zb = z + (size_t)b * D_ * HW_ + hw0;

        // ---- stage A: z fp32 -> smem (padded) + bf16 hi/lo SW128 ----
        {
            const int c0s = q4 * 16;
            #pragma unroll
            for (int j = 0; j < 8; j++) {
                int c = c0s + 2 * j;
                float v0 = __ldg(zb + (size_t)c * HW_ + p);
                float v1 = __ldg(zb + (size_t)(c + 1) * HW_ + p);
                s_z[p * 65 + c]     = v0;
                s_z[p * 65 + c + 1] = v1;
                float h0 = __bfloat162float(__float2bfloat16(v0));
                float h1 = __bfloat162float(__float2bfloat16(v1));
                uint32_t off = (uint32_t)(p * 128 + c * 2);
                *(uint32_t*)(smem + SM_AHI + SWZ128(off)) = pack_bf16x2(h0, h1);
                *(uint32_t*)(smem + SM_ALO + SWZ128(off)) = pack_bf16x2(v0 - h0, v1 - h1);
            }
        }
        __syncthreads();

        // ---- A fragments (validated layout) ----
        uint32_t ah[4][4], al[4][4];
        #pragma unroll
        for (int ks = 0; ks < 4; ks++) {
            uint32_t o = (uint32_t)(row0 * 128 + ks * 32 + tg * 4);
            ah[ks][0] = *(uint32_t*)(smem + SM_AHI + SWZ128(o));
            ah[ks][1] = *(uint32_t*)(smem + SM_AHI + SWZ128(o + 8 * 128));
            ah[ks][2] = *(uint32_t*)(smem + SM_AHI + SWZ128(o + 16));
            ah[ks][3] = *(uint32_t*)(smem + SM_AHI + SWZ128(o + 8 * 128 + 16));
            al[ks][0] = *(uint32_t*)(smem + SM_ALO + SWZ128(o));
            al[ks][1] = *(uint32_t*)(smem + SM_ALO + SWZ128(o + 8 * 128));
            al[ks][2] = *(uint32_t*)(smem + SM_ALO + SWZ128(o + 16));
            al[ks][3] = *(uint32_t*)(smem + SM_ALO + SWZ128(o + 8 * 128 + 16));
        }

        uint32_t bh0 = smb + SM_BH + browz + colx0;
        uint32_t bh1 = smb + SM_BH + browz + colx1;
        uint32_t bl0 = smb + SM_BL + browz + colx0;
        uint32_t bl1 = smb + SM_BL + browz + colx1;

        float m1a = 3.4e38f, m2a = 3.4e38f;
        float m1b = 3.4e38f, m2b = 3.4e38f;
        int   k1a = K_, k1b = K_;

        #pragma unroll 4
        for (int nb = 0; nb < 32; nb++) {
            uint32_t h1[4], h2[4], lo1[4], lo2[4];
            ldsm_x4(h1,  bh0); ldsm_x4(h2,  bh1);
            ldsm_x4(lo1, bl0); ldsm_x4(lo2, bl1);
            bh0 += 1024; bh1 += 1024; bl0 += 1024; bl1 += 1024;

            // 3 independent accumulator chains (ILP) -- summed below.
            float chh[4] = {0.f, 0.f, 0.f, 0.f};   // ah * bh
            float clh[4] = {0.f, 0.f, 0.f, 0.f};   // al * bh
            float chl[4] = {0.f, 0.f, 0.f, 0.f};   // ah * bl
            mma_bf16(chh, ah[0], h1[0], h1[1]);
            mma_bf16(clh, al[0], h1[0], h1[1]);
            mma_bf16(chl, ah[0], lo1[0], lo1[1]);
            mma_bf16(chh, ah[1], h1[2], h1[3]);
            mma_bf16(clh, al[1], h1[2], h1[3]);
            mma_bf16(chl, ah[1], lo1[2], lo1[3]);
            mma_bf16(chh, ah[2], h2[0], h2[1]);
            mma_bf16(clh, al[2], h2[0], h2[1]);
            mma_bf16(chl, ah[2], lo2[0], lo2[1]);
            mma_bf16(chh, ah[3], h2[2], h2[3]);
            mma_bf16(clh, al[3], h2[2], h2[3]);
            mma_bf16(chl, ah[3], lo2[2], lo2[3]);

            const int c0 = nh * 256 + nb * 8 + tg * 2;
            float2 y2 = *(const float2*)&s_y[c0];
            float t0 = fmaf(-2.f, (chh[0] + clh[0]) + chl[0], y2.x);
            float t1 = fmaf(-2.f, (chh[1] + clh[1]) + chl[1], y2.y);
            float t2 = fmaf(-2.f, (chh[2] + clh[2]) + chl[2], y2.x);
            float t3 = fmaf(-2.f, (chh[3] + clh[3]) + chl[3], y2.y);
            if (t0 < m1a) { m2a = m1a; m1a = t0; k1a = c0; }     else m2a = fminf(m2a, t0);
            if (t1 < m1a) { m2a = m1a; m1a = t1; k1a = c0 + 1; } else m2a = fminf(m2a, t1);
            if (t2 < m1b) { m2b = m1b; m1b = t2; k1b = c0; }     else m2b = fminf(m2b, t2);
            if (t3 < m1b) { m2b = m1b; m1b = t3; k1b = c0 + 1; } else m2b = fminf(m2b, t3);
        }

        // quad merge (tg bits)
        #pragma unroll
        for (int off = 1; off <= 2; off <<= 1) {
            float om1 = __shfl_xor_sync(0xffffffffu, m1a, off);
            int   ok1 = __shfl_xor_sync(0xffffffffu, k1a, off);
            float om2 = __shfl_xor_sync(0xffffffffu, m2a, off);
            merge3(m1a, k1a, m2a, om1, ok1, om2);
            om1 = __shfl_xor_sync(0xffffffffu, m1b, off);
            ok1 = __shfl_xor_sync(0xffffffffu, k1b, off);
            om2 = __shfl_xor_sync(0xffffffffu, m2b, off);
            merge3(m1b, k1b, m2b, om1, ok1, om2);
        }
        if (tg == 0) {
            s_m1[row0 * 2 + nh] = m1a; s_m2[row0 * 2 + nh] = m2a;
            s_k1[row0 * 2 + nh] = k1a;
            s_m1[(row0 + 8) * 2 + nh] = m1b; s_m2[(row0 + 8) * 2 + nh] = m2b;
            s_k1[(row0 + 8) * 2 + nh] = k1b;
        }
        __syncthreads();

        // ---- decision: merge halves, window -> worklist ----
        if (tid < 128) {
            float m1 = s_m1[tid * 2], m2v = s_m2[tid * 2];
            int   k1 = s_k1[tid * 2];
            merge3(m1, k1, m2v, s_m1[tid*2+1], s_k1[tid*2+1], s_m2[tid*2+1]);
            int fl = (m2v - m1) < W0;
            s_bkf[tid] = k1; s_flag[tid] = fl;
            if (fl) {
                int i = atomicAdd(&g_flag_count, 1);
                g_worklist[i] = base + tid;
            }
        }
        __syncthreads();

        // ---- output + loss (z from smem, codebook via LDG.128) ----
        float lsum = 0.f;
        if (!s_flag[p]) {
            const int bestk = s_bkf[p];
            const float4* e4 = (const float4*)(cb + bestk * D_);
            float* op = out + (size_t)b * D_ * HW_ + hw0 + p;
            #pragma unroll
            for (int j4 = 0; j4 < 4; j4++) {
                float4 e = __ldg(e4 + q4 * 4 + j4);
                #pragma unroll
                for (int u = 0; u < 4; u++) {
                    int c = q4 * 16 + 4 * j4 + u;
                    float qq = (u == 0) ? e.x : (u == 1) ? e.y : (u == 2) ? e.z : e.w;
                    float zv = s_z[p * 65 + c];
                    float dd = __fadd_rn(qq, -zv);
                    lsum = __fmaf_rn(dd, dd, lsum);
                    op[(size_t)c * HW_] = __fadd_rn(zv, dd);
                }
            }
        }
        #pragma unroll
        for (int off = 16; off > 0; off >>= 1)
            lsum += __shfl_down_sync(0xffffffffu, lsum, off);
        if (lane == 0) s_red[wid] = lsum;
        __syncthreads();
        if (tid == 0) {
            float v = 0.f;
            #pragma unroll
            for (int i = 0; i < 16; i++) v += s_red[i];
            atomicAdd(&g_loss_accum, (double)v);
        }
        __syncthreads();   // protect smem tiles before next tile's staging
    }
}

// ---------------- fallback: bit-exact full scan, one point per warp ----------------
#define FB_CTAS 64
#define FB_TPB  256
__global__ __launch_bounds__(FB_TPB)
void vq_fallback_kernel(const float* __restrict__ z,
                        const float* __restrict__ cb,
                        float* __restrict__ out) {
    const int lane = threadIdx.x & 31;
    const int gw   = (blockIdx.x * FB_TPB + threadIdx.x) >> 5;
    const int nw   = (FB_CTAS * FB_TPB) >> 5;
    const int cnt  = g_flag_count;

    for (int w = gw; w < cnt; w += nw) {
        const int n  = g_worklist[w];
        const int b  = n >> 12;
        const int hw = n & (HW_ - 1);
        const float* zp = z + (size_t)b * D_ * HW_ + hw;

        float zv[D_];
        #pragma unroll
        for (int i = 0; i < D_; i++) zv[i] = __ldg(zp + (size_t)i * HW_);
        float x = 0.f;
        #pragma unroll
        for (int i = 0; i < D_; i++) x = __fadd_rn(x, __fmul_rn(zv[i], zv[i]));

        // 4 codes concurrently (independent exact chains, per-code order preserved)
        float bd = 3.4e38f; int bk = K_;
        #pragma unroll 1
        for (int kk = 0; kk < 16; kk += 4) {
            const int k = lane * 16 + kk;
            const float4* r0 = (const float4*)(cb + (k + 0) * D_);
            const float4* r1 = (const float4*)(cb + (k + 1) * D_);
            const float4* r2 = (const float4*)(cb + (k + 2) * D_);
            const float4* r3 = (const float4*)(cb + (k + 3) * D_);
            float a0 = 0.f, a1 = 0.f, a2 = 0.f, a3 = 0.f;
            #pragma unroll
            for (int i = 0; i < 16; i++) {
                float4 e0 = __ldg(r0 + i), e1 = __ldg(r1 + i);
                float4 e2 = __ldg(r2 + i), e3 = __ldg(r3 + i);
                a0 = __fmaf_rn(zv[4*i+0], e0.x, a0);
                a1 = __fmaf_rn(zv[4*i+0], e1.x, a1);
                a2 = __fmaf_rn(zv[4*i+0], e2.x, a2);
                a3 = __fmaf_rn(zv[4*i+0], e3.x, a3);
                a0 = __fmaf_rn(zv[4*i+1], e0.y, a0);
                a1 = __fmaf_rn(zv[4*i+1], e1.y, a1);
                a2 = __fmaf_rn(zv[4*i+1], e2.y, a2);
                a3 = __fmaf_rn(zv[4*i+1], e3.y, a3);
                a0 = __fmaf_rn(zv[4*i+2], e0.z, a0);
                a1 = __fmaf_rn(zv[4*i+2], e1.z, a1);
                a2 = __fmaf_rn(zv[4*i+2], e2.z, a2);
                a3 = __fmaf_rn(zv[4*i+2], e3.z, a3);
                a0 = __fmaf_rn(zv[4*i+3], e0.w, a0);
                a1 = __fmaf_rn(zv[4*i+3], e1.w, a1);
                a2 = __fmaf_rn(zv[4*i+3], e2.w, a2);
                a3 = __fmaf_rn(zv[4*i+3], e3.w, a3);
            }
            float d0 = __fadd_rn(__fadd_rn(x, g_y[k + 0]), -__fmul_rn(2.f, a0));
            float d1 = __fadd_rn(__fadd_rn(x, g_y[k + 1]), -__fmul_rn(2.f, a1));
            float d2 = __fadd_rn(__fadd_rn(x, g_y[k + 2]), -__fmul_rn(2.f, a2));
            float d3 = __fadd_rn(__fadd_rn(x, g_y[k + 3]), -__fmul_rn(2.f, a3));
            if (d0 < bd) { bd = d0; bk = k + 0; }
            if (d1 < bd) { bd = d1; bk = k + 1; }
            if (d2 < bd) { bd = d2; bk = k + 2; }
            if (d3 < bd) { bd = d3; bk = k + 3; }
        }
        #pragma unroll
        for (int off = 16; off > 0; off >>= 1) {
            float od = __shfl_down_sync(0xffffffffu, bd, off);
            int   ok = __shfl_down_sync(0xffffffffu, bk, off);
            if (od < bd || (od == bd && ok < bk)) { bd = od; bk = ok; }
        }
        bk = __shfl_sync(0xffffffffu, bk, 0);

        float* op = out + (size_t)b * D_ * HW_ + hw;
        const float* e = cb + bk * D_;
        float ls = 0.f;
        #pragma unroll
        for (int h = 0; h < 2; h++) {
            int c = lane + 32 * h;
            float qq = __ldg(e + c);
            float dd = __fadd_rn(qq, -zv[c]);
            ls = __fmaf_rn(dd, dd, ls);
            op[(size_t)c * HW_] = __fadd_rn(zv[c], dd);
        }
        #pragma unroll
        for (int off = 16; off > 0; off >>= 1)
            ls += __shfl_down_sync(0xffffffffu, ls, off);
        if (lane == 0) atomicAdd(&g_loss_accum, (double)ls);
    }
}

// ---------------- finalize: write loss, reset state for graph replays ----------------
__global__ void vq_finalize_kernel(float* __restrict__ out, int loss_idx) {
    out[loss_idx] = (float)(g_loss_accum * 1.25 / (double)NELEM);
    g_loss_accum = 0.0;
    g_flag_count = 0;
}

extern "C" void kernel_launch(void* const* d_in, const int* in_sizes, int n_in,
                              void* d_out, int out_size) {
    const float* z  = (const float*)d_in[0];
    const float* cb = (const float*)d_in[1];
    float* out = (float*)d_out;

    static bool attr_set = false;
    if (!attr_set) {
        cudaFuncSetAttribute(vq_main_kernel,
                             cudaFuncAttributeMaxDynamicSharedMemorySize,
                             SMEM_TOTAL);
        attr_set = true;
    }

    vq_main_kernel<<<MGRID, MTPB, SMEM_TOTAL>>>(z, cb, out);
    vq_fallback_kernel<<<FB_CTAS, FB_TPB>>>(z, cb, out);
    vq_finalize_kernel<<<1, 1>>>(out, out_size - 1);
}